// round 11
// baseline (speedup 1.0000x reference)
#include <cuda_runtime.h>
#include <cstdint>

#define E        300
#define E4       75
#define SEQ      2048
#define BATCH    64
#define CPB      8
#define TOK_PER_CTA 256
#define TOK_PER_WARP 16
#define NSTEP    8       // 2 tokens per step
#define ATTN_H   150
#define NC       34
#define PSTRIDE  304     // h[0..300), l@300, pad
#define THREADS_P 512
#define NWARP    16

__device__ __align__(16) float g_part[BATCH * CPB * PSTRIDE];
__device__ __align__(16) float g_h1[BATCH * E];
__device__ __align__(16) float g_r [BATCH * E];
__device__ int g_cnt[2][BATCH];   // zero-init; winner self-resets each launch

__device__ __forceinline__ float dot4(float4 a, float4 b) {
    return a.x * b.x + a.y * b.y + a.z * b.z + a.w * b.w;
}

// ---------------------------------------------------------------------------
// Fused stage kernel. grid=(CPB,BATCH), 512 thr, 2 CTAs/SM.
// Warp-autonomous register-resident mainloop: 2 independent tokens per step
// (two interleaved shfl-reduce chains, 6 LDG.128 in flight), direct LDGs,
// no smem staging, no online-max (scores are O(1) => raw exp safe).
//   STAGE 1: h1 -> g_h1;  r = Wat @ (h1 @ Wat) -> g_r
//   STAGE 2: h2;          out = [h1,h2] @ Wout + bias  (last CTA per batch)
// ---------------------------------------------------------------------------
template<int STAGE>
__global__ __launch_bounds__(THREADS_P, 2) void fused_stage_kernel(
    const int* __restrict__ input_x,
    const float* __restrict__ emb,
    const float* __restrict__ q_in,
    const float* __restrict__ Wat,
    const float* __restrict__ Wout,
    const float* __restrict__ bias,
    float* __restrict__ out)
{
    __shared__ float4 wacc[NWARP * 76];       // 19 KB: warp partial h
    __shared__ float  ll[NWARP];
    __shared__ float  hs[E], h1s[E];
    __shared__ float  q2part[NWARP][152];
    __shared__ float  q2s[152];
    __shared__ float  opart[NWARP][NC];
    __shared__ int    isLast;

    const int slice = blockIdx.x;
    const int b     = blockIdx.y;
    const int tid   = threadIdx.x;
    const int w     = tid >> 5;
    const int lane  = tid & 31;
    const float scale = (STAGE == 1) ? 0.05773502691896258f : 1.0f;
    const float4* __restrict__ emb4 = (const float4*)emb;
    const float4 fz = make_float4(0.f, 0.f, 0.f, 0.f);

    // Per-batch query in registers
    const float* qp = (STAGE == 1) ? q_in : (g_r + b * E);
    const float4* qp4 = (const float4*)qp;
    float4 qa = qp4[lane];
    float4 qb = qp4[lane + 32];
    float4 qc = (lane < 11) ? qp4[lane + 64] : fz;

    // This warp's 16 token indices (lanes 16-31 read duplicates; broadcast)
    const int myidx = input_x[b * SEQ + slice * TOK_PER_CTA
                              + w * TOK_PER_WARP + (lane & 15)];

    float l = 0.f;
    float4 A = fz, B = fz, C = fz;

    #pragma unroll 1
    for (int s = 0; s < NSTEP; s++) {
        int r0 = __shfl_sync(0xffffffffu, myidx, 2 * s);
        int r1 = __shfl_sync(0xffffffffu, myidx, 2 * s + 1);
        const float4* p0 = emb4 + (long long)r0 * E4;
        const float4* p1 = emb4 + (long long)r1 * E4;
        float4 a0 = p0[lane], b0 = p0[lane + 32];
        float4 a1 = p1[lane], b1 = p1[lane + 32];
        float4 c0 = fz, c1 = fz;
        if (lane < 11) { c0 = p0[lane + 64]; c1 = p1[lane + 64]; }

        float s0 = dot4(a0, qa) + dot4(b0, qb) + dot4(c0, qc);
        float s1 = dot4(a1, qa) + dot4(b1, qb) + dot4(c1, qc);
        #pragma unroll
        for (int o = 16; o; o >>= 1) {
            s0 += __shfl_xor_sync(0xffffffffu, s0, o);
            s1 += __shfl_xor_sync(0xffffffffu, s1, o);
        }

        float w0 = __expf(s0 * scale);
        float w1 = __expf(s1 * scale);
        l += w0 + w1;
        A.x += w0 * a0.x + w1 * a1.x;  A.y += w0 * a0.y + w1 * a1.y;
        A.z += w0 * a0.z + w1 * a1.z;  A.w += w0 * a0.w + w1 * a1.w;
        B.x += w0 * b0.x + w1 * b1.x;  B.y += w0 * b0.y + w1 * b1.y;
        B.z += w0 * b0.z + w1 * b1.z;  B.w += w0 * b0.w + w1 * b1.w;
        C.x += w0 * c0.x + w1 * c1.x;  C.y += w0 * c0.y + w1 * c1.y;
        C.z += w0 * c0.z + w1 * c1.z;  C.w += w0 * c0.w + w1 * c1.w;
    }

    // ---- CTA merge of 16 warp partials (pure sums)
    if (lane == 0) ll[w] = l;
    wacc[w * 76 + lane]      = A;
    wacc[w * 76 + lane + 32] = B;
    if (lane < 11) wacc[w * 76 + lane + 64] = C;
    __syncthreads();

    float* p = g_part + (b * CPB + slice) * PSTRIDE;
    if (tid < E4) {
        float4 ssum = fz;
        #pragma unroll
        for (int i = 0; i < NWARP; i++) {
            float4 v = wacc[i * 76 + tid];
            ssum.x += v.x; ssum.y += v.y; ssum.z += v.z; ssum.w += v.w;
        }
        ((float4*)p)[tid] = ssum;
    }
    if (tid == 0) {
        float Ls = 0.f;
        #pragma unroll
        for (int i = 0; i < NWARP; i++) Ls += ll[i];
        p[300] = Ls;
    }

    // ---- Last CTA per batch merges CPB partials + epilogue
    __syncthreads();
    if (tid == 0) {
        __threadfence();
        int old = atomicAdd(&g_cnt[STAGE - 1][b], 1);
        isLast = (old == CPB - 1);
        if (isLast) g_cnt[STAGE - 1][b] = 0;   // self-reset for graph replay
    }
    __syncthreads();
    if (!isLast) return;
    __threadfence();

    const float* pb = g_part + b * CPB * PSTRIDE;
    if (tid == 0) {
        float Lg = 0.f;
        #pragma unroll
        for (int i = 0; i < CPB; i++) Lg += pb[i * PSTRIDE + 300];
        q2s[151] = 1.f / Lg;     // stash invL in shared
    }
    __syncthreads();
    const float invL = q2s[151];

    if (tid < E) {
        float s = 0.f;
        #pragma unroll
        for (int i = 0; i < CPB; i++) s += pb[i * PSTRIDE + tid];
        s *= invL;
        hs[tid] = s;
        if (STAGE == 1) g_h1[b * E + tid] = s;
        else            h1s[tid] = g_h1[b * E + tid];
    }
    __syncthreads();

    if (STAGE == 1) {
        // q2 = h1 @ Wat — 16-warp split over e, 5 chains/lane
        float a5[5] = {0.f, 0.f, 0.f, 0.f, 0.f};
        for (int e = w; e < E; e += NWARP) {
            float hv = hs[e];
            const float* wr = Wat + e * ATTN_H;
            #pragma unroll
            for (int c = 0; c < 5; c++) {
                int h = lane + 32 * c;
                if (h < ATTN_H) a5[c] += hv * wr[h];
            }
        }
        #pragma unroll
        for (int c = 0; c < 5; c++) {
            int h = lane + 32 * c;
            if (h < ATTN_H) q2part[w][h] = a5[c];
        }
        __syncthreads();
        if (tid < ATTN_H) {
            float s = 0.f;
            #pragma unroll
            for (int i = 0; i < NWARP; i++) s += q2part[i][tid];
            q2s[tid] = s;
        }
        __syncthreads();

        // r = Wat @ q2 — warp per (e0, e0+16)
        for (int e0 = w; e0 < E; e0 += 32) {
            int e1 = e0 + 16;
            float s0 = 0.f, s1 = 0.f;
            const float* w0p = Wat + e0 * ATTN_H;
            const float* w1p = Wat + e1 * ATTN_H;
            #pragma unroll
            for (int c = 0; c < 5; c++) {
                int h = lane + 32 * c;
                if (h < ATTN_H) {
                    float qv = q2s[h];
                    s0 += qv * w0p[h];
                    if (e1 < E) s1 += qv * w1p[h];
                }
            }
            #pragma unroll
            for (int o = 16; o; o >>= 1) {
                s0 += __shfl_xor_sync(0xffffffffu, s0, o);
                s1 += __shfl_xor_sync(0xffffffffu, s1, o);
            }
            if (lane == 0) {
                g_r[b * E + e0] = s0;
                if (e1 < E) g_r[b * E + e1] = s1;
            }
        }
    } else {
        // out = [h1, h2] @ Wout + bias — 16-warp split over 600 rows
        float o0 = 0.f, o1 = 0.f;
        for (int e = w; e < 2 * E; e += NWARP) {
            float hv = (e < E) ? h1s[e] : hs[e - E];
            const float* wr = Wout + e * NC;
            o0 += hv * wr[lane];
            if (lane < NC - 32) o1 += hv * wr[32 + lane];
        }
        opart[w][lane] = o0;
        if (lane < NC - 32) opart[w][32 + lane] = o1;
        __syncthreads();
        if (tid < NC) {
            float s = bias[tid];
            #pragma unroll
            for (int i = 0; i < NWARP; i++) s += opart[i][tid];
            out[b * NC + tid] = s;
        }
    }
}

extern "C" void kernel_launch(void* const* d_in, const int* in_sizes, int n_in,
                              void* d_out, int out_size)
{
    const int*   input_x = (const int*)  d_in[0];
    const float* emb     = (const float*)d_in[1];
    const float* query   = (const float*)d_in[2];
    const float* Wat     = (const float*)d_in[3];
    const float* Wout    = (const float*)d_in[4];
    const float* bias    = (const float*)d_in[5];
    float*       outp    = (float*)d_out;

    dim3 grid(CPB, BATCH);
    fused_stage_kernel<1><<<grid, THREADS_P>>>(
        input_x, emb, query, Wat, Wout, bias, outp);
    fused_stage_kernel<2><<<grid, THREADS_P>>>(
        input_x, emb, query, Wat, Wout, bias, outp);
}

// round 12
// speedup vs baseline: 1.0864x; 1.0864x over previous
#include <cuda_runtime.h>
#include <cstdint>

#define E        300
#define E4       75
#define SEQ      2048
#define BATCH    64
#define CPB      4
#define TOK_PER_CTA 512
#define TOK_PER_WARP 32
#define ATTN_H   150
#define NC       34
#define PSTRIDE  304     // h[0..300), l@300, pad
#define THREADS_P 512
#define NWARP    16

typedef unsigned long long u64;

__device__ __align__(16) float g_part[BATCH * CPB * PSTRIDE];
__device__ __align__(16) float g_h1[BATCH * E];
__device__ __align__(16) float g_r [BATCH * E];
__device__ int g_cnt[2][BATCH];   // zero-init; winner self-resets each launch

__device__ __forceinline__ u64 pk2(float lo, float hi) {
    u64 r; asm("mov.b64 %0, {%1, %2};" : "=l"(r) : "f"(lo), "f"(hi)); return r;
}
__device__ __forceinline__ void upk2(u64 v, float& lo, float& hi) {
    asm("mov.b64 {%0, %1}, %2;" : "=f"(lo), "=f"(hi) : "l"(v));
}
__device__ __forceinline__ u64 fma2(u64 a, u64 b, u64 c) {
    u64 r; asm("fma.rn.f32x2 %0, %1, %2, %3;" : "=l"(r) : "l"(a), "l"(b), "l"(c));
    return r;
}

// ---------------------------------------------------------------------------
// Fused stage kernel. grid=(CPB,BATCH), 512 thr, 2 CTAs/SM.
// R10 structure (1 token/step, prefetch-1, direct LDG.128, no online-max)
// with all mainloop arithmetic in packed f32x2 (FFMA2): 6 FFMA2 dot +
// 6 FFMA2 accumulate per token instead of 24 scalar FFMAs.
//   STAGE 1: h1 -> g_h1;  r = Wat @ (h1 @ Wat) -> g_r
//   STAGE 2: h2;          out = [h1,h2] @ Wout + bias  (last CTA per batch)
// ---------------------------------------------------------------------------
template<int STAGE>
__global__ __launch_bounds__(THREADS_P, 2) void fused_stage_kernel(
    const int* __restrict__ input_x,
    const float* __restrict__ emb,
    const float* __restrict__ q_in,
    const float* __restrict__ Wat,
    const float* __restrict__ Wout,
    const float* __restrict__ bias,
    float* __restrict__ out)
{
    __shared__ float4 wacc[NWARP * 76];       // 19 KB: warp partial h
    __shared__ float  ll[NWARP];
    __shared__ float  hs[E], h1s[E];
    __shared__ float  q2part[NWARP][152];
    __shared__ float  q2s[152];
    __shared__ float  opart[NWARP][NC];
    __shared__ int    isLast;

    const int slice = blockIdx.x;
    const int b     = blockIdx.y;
    const int tid   = threadIdx.x;
    const int w     = tid >> 5;
    const int lane  = tid & 31;
    const float scale = (STAGE == 1) ? 0.05773502691896258f : 1.0f;
    const ulonglong2* __restrict__ embu = (const ulonglong2*)emb;
    ulonglong2 uz; uz.x = 0ull; uz.y = 0ull;

    // Per-batch query in packed registers, pre-scaled (folds scale into dot)
    const float* qp = (STAGE == 1) ? q_in : (g_r + b * E);
    const float4* qp4 = (const float4*)qp;
    float4 t0 = qp4[lane];
    float4 t1 = qp4[lane + 32];
    float4 t2 = (lane < 11) ? qp4[lane + 64] : make_float4(0.f, 0.f, 0.f, 0.f);
    const u64 qa0 = pk2(t0.x * scale, t0.y * scale);
    const u64 qa1 = pk2(t0.z * scale, t0.w * scale);
    const u64 qb0 = pk2(t1.x * scale, t1.y * scale);
    const u64 qb1 = pk2(t1.z * scale, t1.w * scale);
    const u64 qc0 = pk2(t2.x * scale, t2.y * scale);
    const u64 qc1 = pk2(t2.z * scale, t2.w * scale);

    // This warp's 32 token indices
    const int myidx = input_x[b * SEQ + slice * TOK_PER_CTA + w * TOK_PER_WARP + lane];

    float l = 0.f;
    u64 Ax = 0ull, Ay = 0ull, Bx = 0ull, By = 0ull, Cx = 0ull, Cy = 0ull;

    int row0 = __shfl_sync(0xffffffffu, myidx, 0);
    const ulonglong2* sp = embu + (long long)row0 * E4;
    ulonglong2 na = sp[lane];
    ulonglong2 nb = sp[lane + 32];
    ulonglong2 nc = (lane < 11) ? sp[lane + 64] : uz;

    #pragma unroll 4
    for (int t = 0; t < TOK_PER_WARP; t++) {
        ulonglong2 ca = na, cb = nb, cc = nc;
        if (t + 1 < TOK_PER_WARP) {
            int rn = __shfl_sync(0xffffffffu, myidx, t + 1);
            const ulonglong2* np = embu + (long long)rn * E4;
            na = np[lane];
            nb = np[lane + 32];
            if (lane < 11) nc = np[lane + 64];
        }

        // Packed dot: 6 FFMA2
        u64 pa = fma2(ca.x, qa0, 0ull);
        pa = fma2(ca.y, qa1, pa);
        pa = fma2(cb.x, qb0, pa);
        pa = fma2(cb.y, qb1, pa);
        pa = fma2(cc.x, qc0, pa);
        pa = fma2(cc.y, qc1, pa);
        float lo, hi;
        upk2(pa, lo, hi);
        float s = lo + hi;
        #pragma unroll
        for (int o = 16; o; o >>= 1) s += __shfl_xor_sync(0xffffffffu, s, o);

        float wt = __expf(s);       // scale pre-folded into q
        l += wt;
        u64 ww = pk2(wt, wt);
        Ax = fma2(ca.x, ww, Ax);  Ay = fma2(ca.y, ww, Ay);
        Bx = fma2(cb.x, ww, Bx);  By = fma2(cb.y, ww, By);
        Cx = fma2(cc.x, ww, Cx);  Cy = fma2(cc.y, ww, Cy);
    }

    // ---- CTA merge of 16 warp partials (pure sums)
    if (lane == 0) ll[w] = l;
    ulonglong2* waccu = (ulonglong2*)wacc;
    { ulonglong2 v; v.x = Ax; v.y = Ay; waccu[w * 76 + lane]      = v; }
    { ulonglong2 v; v.x = Bx; v.y = By; waccu[w * 76 + lane + 32] = v; }
    if (lane < 11) { ulonglong2 v; v.x = Cx; v.y = Cy; waccu[w * 76 + lane + 64] = v; }
    __syncthreads();

    float* p = g_part + (b * CPB + slice) * PSTRIDE;
    if (tid < E4) {
        float4 ssum = make_float4(0.f, 0.f, 0.f, 0.f);
        #pragma unroll
        for (int i = 0; i < NWARP; i++) {
            float4 v = wacc[i * 76 + tid];
            ssum.x += v.x; ssum.y += v.y; ssum.z += v.z; ssum.w += v.w;
        }
        ((float4*)p)[tid] = ssum;
    }
    if (tid == 0) {
        float Ls = 0.f;
        #pragma unroll
        for (int i = 0; i < NWARP; i++) Ls += ll[i];
        p[300] = Ls;
    }

    // ---- Last CTA per batch merges CPB partials + epilogue
    __syncthreads();
    if (tid == 0) {
        __threadfence();
        int old = atomicAdd(&g_cnt[STAGE - 1][b], 1);
        isLast = (old == CPB - 1);
        if (isLast) g_cnt[STAGE - 1][b] = 0;   // self-reset for graph replay
    }
    __syncthreads();
    if (!isLast) return;
    __threadfence();

    const float* pb = g_part + b * CPB * PSTRIDE;
    if (tid == 0) {
        float Lg = 0.f;
        #pragma unroll
        for (int i = 0; i < CPB; i++) Lg += pb[i * PSTRIDE + 300];
        q2s[151] = 1.f / Lg;     // stash invL in shared
    }
    __syncthreads();
    const float invL = q2s[151];

    if (tid < E) {
        float s = 0.f;
        #pragma unroll
        for (int i = 0; i < CPB; i++) s += pb[i * PSTRIDE + tid];
        s *= invL;
        hs[tid] = s;
        if (STAGE == 1) g_h1[b * E + tid] = s;
        else            h1s[tid] = g_h1[b * E + tid];
    }
    __syncthreads();

    if (STAGE == 1) {
        // q2 = h1 @ Wat — 16-warp split over e, 5 chains/lane
        float a5[5] = {0.f, 0.f, 0.f, 0.f, 0.f};
        for (int e = w; e < E; e += NWARP) {
            float hv = hs[e];
            const float* wr = Wat + e * ATTN_H;
            #pragma unroll
            for (int c = 0; c < 5; c++) {
                int h = lane + 32 * c;
                if (h < ATTN_H) a5[c] += hv * wr[h];
            }
        }
        #pragma unroll
        for (int c = 0; c < 5; c++) {
            int h = lane + 32 * c;
            if (h < ATTN_H) q2part[w][h] = a5[c];
        }
        __syncthreads();
        if (tid < ATTN_H) {
            float s = 0.f;
            #pragma unroll
            for (int i = 0; i < NWARP; i++) s += q2part[i][tid];
            q2s[tid] = s;
        }
        __syncthreads();

        // r = Wat @ q2 — warp per (e0, e0+16)
        for (int e0 = w; e0 < E; e0 += 32) {
            int e1 = e0 + 16;
            float s0 = 0.f, s1 = 0.f;
            const float* w0p = Wat + e0 * ATTN_H;
            const float* w1p = Wat + e1 * ATTN_H;
            #pragma unroll
            for (int c = 0; c < 5; c++) {
                int h = lane + 32 * c;
                if (h < ATTN_H) {
                    float qv = q2s[h];
                    s0 += qv * w0p[h];
                    if (e1 < E) s1 += qv * w1p[h];
                }
            }
            #pragma unroll
            for (int o = 16; o; o >>= 1) {
                s0 += __shfl_xor_sync(0xffffffffu, s0, o);
                s1 += __shfl_xor_sync(0xffffffffu, s1, o);
            }
            if (lane == 0) {
                g_r[b * E + e0] = s0;
                if (e1 < E) g_r[b * E + e1] = s1;
            }
        }
    } else {
        // out = [h1, h2] @ Wout + bias — 16-warp split over 600 rows
        float o0 = 0.f, o1 = 0.f;
        for (int e = w; e < 2 * E; e += NWARP) {
            float hv = (e < E) ? h1s[e] : hs[e - E];
            const float* wr = Wout + e * NC;
            o0 += hv * wr[lane];
            if (lane < NC - 32) o1 += hv * wr[32 + lane];
        }
        opart[w][lane] = o0;
        if (lane < NC - 32) opart[w][32 + lane] = o1;
        __syncthreads();
        if (tid < NC) {
            float s = bias[tid];
            #pragma unroll
            for (int i = 0; i < NWARP; i++) s += opart[i][tid];
            out[b * NC + tid] = s;
        }
    }
}

extern "C" void kernel_launch(void* const* d_in, const int* in_sizes, int n_in,
                              void* d_out, int out_size)
{
    const int*   input_x = (const int*)  d_in[0];
    const float* emb     = (const float*)d_in[1];
    const float* query   = (const float*)d_in[2];
    const float* Wat     = (const float*)d_in[3];
    const float* Wout    = (const float*)d_in[4];
    const float* bias    = (const float*)d_in[5];
    float*       outp    = (float*)d_out;

    dim3 grid(CPB, BATCH);
    fused_stage_kernel<1><<<grid, THREADS_P>>>(
        input_x, emb, query, Wat, Wout, bias, outp);
    fused_stage_kernel<2><<<grid, THREADS_P>>>(
        input_x, emb, query, Wat, Wout, bias, outp);
}